// round 17
// baseline (speedup 1.0000x reference)
#include <cuda_runtime.h>
#include <cuda_bf16.h>

// DDA_PU_loss: loss = sum_pos((rec-dv)^2)*(1-a)/2 + sum_neg((rec-dv)^2)*a/2
// R17: locality-creating two-phase gather.
//   K1 zero histogram -> K2 count buckets (off>>16) -> K3 scan -> K4 scatter
//   packed offsets into bucket order -> K5 clustered gather + fused reduction.
// Rationale: R16 measured ~644 MB HBM (full 128B line per random 4B gather).
// Bucketing by address recovers the ~25% same-line dedup (lambda=0.625) in L2
// and improves DRAM row locality.

#define KP_N_POS    524288
#define KP_N_NEG    2097152
#define KP_N_TOT    (KP_N_POS + KP_N_NEG)      // 2621440
#define KP_LOG_NV   14                         // N_VIRUS = 16384
#define KP_OFF_MASK 0x07FFFFFFu                // offsets < 2^27
#define KP_NEG_BIT  27
#define KP_NBUCKET  2048                       // bucket = off >> 16

#define KP_BLOCKS   2048
#define KP_THREADS  256
#define KP_NTHREADS (KP_BLOCKS * KP_THREADS)   // 524288

__device__ unsigned g_cnt[KP_NBUCKET];
__device__ unsigned g_cursor[KP_NBUCKET];
__device__ unsigned g_scratch[KP_N_TOT];       // 10.5 MB packed (off | neg<<27)
__device__ float    g_partials[KP_BLOCKS];
__device__ unsigned g_ticket = 0;

__device__ __forceinline__ float ld_cg(const float* p) {
    float v;
    asm("ld.global.cg.f32 %0, [%1];" : "=f"(v) : "l"(p));
    return v;
}

// ---------------- K1: zero histogram ----------------
__global__ void k_zero()
{
    unsigned i = blockIdx.x * blockDim.x + threadIdx.x;
    if (i < KP_NBUCKET) g_cnt[i] = 0;
}

// ---------------- K2: histogram ----------------
__global__ __launch_bounds__(KP_THREADS)
void k_count(const int* __restrict__ px, const int* __restrict__ py,
             const int* __restrict__ nx, const int* __restrict__ ny)
{
    const unsigned t = blockIdx.x * KP_THREADS + threadIdx.x;   // 0..524287

    unsigned off0 = ((unsigned)__ldg(&px[t]) << KP_LOG_NV) + (unsigned)__ldg(&py[t]);
    const int4 nxv = __ldg((const int4*)nx + t);
    const int4 nyv = __ldg((const int4*)ny + t);

    atomicAdd(&g_cnt[off0 >> 16], 1u);
    atomicAdd(&g_cnt[(((unsigned)nxv.x << KP_LOG_NV) + (unsigned)nyv.x) >> 16], 1u);
    atomicAdd(&g_cnt[(((unsigned)nxv.y << KP_LOG_NV) + (unsigned)nyv.y) >> 16], 1u);
    atomicAdd(&g_cnt[(((unsigned)nxv.z << KP_LOG_NV) + (unsigned)nyv.z) >> 16], 1u);
    atomicAdd(&g_cnt[(((unsigned)nxv.w << KP_LOG_NV) + (unsigned)nyv.w) >> 16], 1u);
}

// ---------------- K3: exclusive scan of 2048 counters (1 block) ----------------
__global__ __launch_bounds__(1024)
void k_scan()
{
    __shared__ unsigned s[1024];
    const int tid = threadIdx.x;

    unsigned c0 = g_cnt[2 * tid];
    unsigned c1 = g_cnt[2 * tid + 1];
    unsigned pair = c0 + c1;
    s[tid] = pair;
    __syncthreads();

    // Hillis-Steele inclusive scan over 1024 pair sums
#pragma unroll
    for (int off = 1; off < 1024; off <<= 1) {
        unsigned v = (tid >= off) ? s[tid - off] : 0u;
        __syncthreads();
        s[tid] += v;
        __syncthreads();
    }
    unsigned excl_pair = s[tid] - pair;
    g_cursor[2 * tid]     = excl_pair;
    g_cursor[2 * tid + 1] = excl_pair + c0;
}

// ---------------- K4: scatter packed offsets into bucket order ----------------
__global__ __launch_bounds__(KP_THREADS)
void k_scatter(const int* __restrict__ px, const int* __restrict__ py,
               const int* __restrict__ nx, const int* __restrict__ ny)
{
    const unsigned t = blockIdx.x * KP_THREADS + threadIdx.x;

    unsigned off0 = ((unsigned)__ldg(&px[t]) << KP_LOG_NV) + (unsigned)__ldg(&py[t]);
    const int4 nxv = __ldg((const int4*)nx + t);
    const int4 nyv = __ldg((const int4*)ny + t);
    unsigned noff[4];
    noff[0] = ((unsigned)nxv.x << KP_LOG_NV) + (unsigned)nyv.x;
    noff[1] = ((unsigned)nxv.y << KP_LOG_NV) + (unsigned)nyv.y;
    noff[2] = ((unsigned)nxv.z << KP_LOG_NV) + (unsigned)nyv.z;
    noff[3] = ((unsigned)nxv.w << KP_LOG_NV) + (unsigned)nyv.w;

    unsigned s0 = atomicAdd(&g_cursor[off0 >> 16], 1u);
    g_scratch[s0] = off0;                                   // pos: bit27 = 0
#pragma unroll
    for (int k = 0; k < 4; k++) {
        unsigned s = atomicAdd(&g_cursor[noff[k] >> 16], 1u);
        g_scratch[s] = noff[k] | (1u << KP_NEG_BIT);        // neg: bit27 = 1
    }
}

// ---------------- K5: clustered gather + fused reduction ----------------
__global__ __launch_bounds__(KP_THREADS, 8)
void k_gather(const float* __restrict__ rec,
              const float* __restrict__ dv,
              const float* __restrict__ alpha_p,
              float* __restrict__ out)
{
    const unsigned t = blockIdx.x * KP_THREADS + threadIdx.x;  // 0..524287

    // 5 packed entries per thread, coalesced; block ~= one address bucket
    unsigned pk[5], offs[5], isneg[5];
#pragma unroll
    for (int k = 0; k < 5; k++) {
        pk[k]    = __ldg(&g_scratch[t + (unsigned)k * KP_NTHREADS]);
        offs[k]  = pk[k] & KP_OFF_MASK;
        isneg[k] = pk[k] >> KP_NEG_BIT;
    }

    // 10 independent clustered gathers, front-batched
    float r[5], d[5];
#pragma unroll
    for (int k = 0; k < 5; k++) { r[k] = ld_cg(rec + offs[k]); d[k] = ld_cg(dv + offs[k]); }

    const float alpha = __ldg(alpha_p);
    const float wp = (1.0f - alpha) * 0.5f;
    const float wn = alpha * 0.5f;

    float sum = 0.0f;
#pragma unroll
    for (int k = 0; k < 5; k++) {
        float df = r[k] - d[k];
        float w  = isneg[k] ? wn : wp;
        sum = fmaf(w * df, df, sum);
    }

    // block reduce
#pragma unroll
    for (int o = 16; o > 0; o >>= 1)
        sum += __shfl_down_sync(0xffffffffu, sum, o);

    __shared__ float warp_sums[KP_THREADS / 32];
    const int lane = threadIdx.x & 31;
    const int wrp  = threadIdx.x >> 5;
    if (lane == 0) warp_sums[wrp] = sum;
    __syncthreads();

    __shared__ bool is_last;
    if (threadIdx.x == 0) {
        float v = warp_sums[0];
#pragma unroll
        for (int i = 1; i < KP_THREADS / 32; i++) v += warp_sums[i];
        g_partials[blockIdx.x] = v;
        __threadfence();
        unsigned prev = atomicAdd(&g_ticket, 1u);
        is_last = (prev == KP_BLOCKS - 1);
    }
    __syncthreads();

    if (is_last) {
        const volatile float* parts = g_partials;
        double v = 0.0;
#pragma unroll
        for (int k = 0; k < KP_BLOCKS / KP_THREADS; k++)
            v += (double)parts[threadIdx.x + k * KP_THREADS];

#pragma unroll
        for (int o = 16; o > 0; o >>= 1)
            v += __shfl_down_sync(0xffffffffu, v, o);

        __shared__ double dws[KP_THREADS / 32];
        if (lane == 0) dws[wrp] = v;
        __syncthreads();

        if (wrp == 0) {
            double s = (lane < KP_THREADS / 32) ? dws[lane] : 0.0;
#pragma unroll
            for (int o = 4; o > 0; o >>= 1)
                s += __shfl_down_sync(0xffu, s, o);
            if (lane == 0) {
                out[0] = (float)s;
                g_ticket = 0;   // reset for next graph replay
            }
        }
    }
}

extern "C" void kernel_launch(void* const* d_in, const int* in_sizes, int n_in,
                              void* d_out, int out_size)
{
    const float* rec     = (const float*)d_in[0];
    const float* dv      = (const float*)d_in[1];
    // d_in[2] = mask, unused (reference ignores it)
    const int*   px      = (const int*)d_in[3];
    const int*   py      = (const int*)d_in[4];
    const int*   nx      = (const int*)d_in[5];
    const int*   ny      = (const int*)d_in[6];
    const float* alpha_p = (const float*)d_in[7];
    float*       out     = (float*)d_out;

    k_zero   <<<(KP_NBUCKET + 255) / 256, 256>>>();
    k_count  <<<KP_BLOCKS, KP_THREADS>>>(px, py, nx, ny);
    k_scan   <<<1, 1024>>>();
    k_scatter<<<KP_BLOCKS, KP_THREADS>>>(px, py, nx, ny);
    k_gather <<<KP_BLOCKS, KP_THREADS>>>(rec, dv, alpha_p, out);
}